// round 16
// baseline (speedup 1.0000x reference)
#include <cuda_runtime.h>
#include <cuda_fp16.h>
#include <math.h>
#include <stdint.h>

// Problem constants
#define Bb 16
#define Ll 128
#define Dd 512
#define Ff 1024
#define Mm 2048

// -------- device scratch (proven safe footprint) --------
__device__ __align__(16) float g_c1[Ll*16];
__device__ __align__(16) float g_c2[Ll*16];
__device__ __align__(16) float g_c3[Ll*16];
__device__ __align__(16) float g_Gg[256*Ff];
__device__ __align__(16) float g_Gu[256*Ff];
__device__ __align__(16) float g_Gd[256*Dd];
__device__ __align__(16) float g_ing[Ll*Ff];
__device__ __align__(16) float g_inu[Ll*Ff];
__device__ __align__(16) float g_ind[Ll*Dd];
__device__ __align__(16) float g_U[Mm*Ff];   // reused: split-K partials 1,2 for O
__device__ __align__(16) float g_V[Mm*Ff];   // reused: split-K partial 3 for O
__device__ __align__(16) float g_H[Mm*Ff];   // h stored as fp16 in first half
__device__ __align__(16) float g_O[Mm*Dd];   // split-K partial 0

// ---------------- PTX helpers ----------------
__device__ __forceinline__ uint32_t smem_u32(const void* p) {
    uint32_t a;
    asm("{ .reg .u64 t; cvta.to.shared.u64 t, %1; cvt.u32.u64 %0, t; }" : "=r"(a) : "l"(p));
    return a;
}
__device__ __forceinline__ void ldsm4(uint32_t* r, uint32_t addr) {
    asm volatile("ldmatrix.sync.aligned.m8n8.x4.shared.b16 {%0,%1,%2,%3}, [%4];"
        : "=r"(r[0]), "=r"(r[1]), "=r"(r[2]), "=r"(r[3]) : "r"(addr));
}
__device__ __forceinline__ void ldsm4t(uint32_t* r, uint32_t addr) {
    asm volatile("ldmatrix.sync.aligned.m8n8.x4.trans.shared.b16 {%0,%1,%2,%3}, [%4];"
        : "=r"(r[0]), "=r"(r[1]), "=r"(r[2]), "=r"(r[3]) : "r"(addr));
}
__device__ __forceinline__ void mmaf16(float* c, const uint32_t* a, const uint32_t* b) {
    asm volatile("mma.sync.aligned.m16n8k16.row.col.f32.f16.f16.f32 "
        "{%0,%1,%2,%3}, {%4,%5,%6,%7}, {%8,%9}, {%0,%1,%2,%3};"
        : "+f"(c[0]), "+f"(c[1]), "+f"(c[2]), "+f"(c[3])
        : "r"(a[0]), "r"(a[1]), "r"(a[2]), "r"(a[3]), "r"(b[0]), "r"(b[1]));
}
__device__ __forceinline__ void sts16(uint32_t addr, uint4 v) {
    asm volatile("st.shared.v4.b32 [%0], {%1,%2,%3,%4};" ::
        "r"(addr), "r"(v.x), "r"(v.y), "r"(v.z), "r"(v.w) : "memory");
}
__device__ __forceinline__ void sts8(uint32_t addr, uint32_t x, uint32_t y) {
    asm volatile("st.shared.v2.b32 [%0], {%1,%2};" :: "r"(addr), "r"(x), "r"(y) : "memory");
}
__device__ __forceinline__ uint32_t hmul2u(uint32_t a, uint32_t b) {
    __half2 r = __hmul2(*(__half2*)&a, *(__half2*)&b);
    return *(uint32_t*)&r;
}

// float4 -> 4 fp16 (8B)
__device__ __forceinline__ void cvt_store4(float4 v, uint32_t addr) {
    __half2 h0 = __float22half2_rn(make_float2(v.x, v.y));
    __half2 h1 = __float22half2_rn(make_float2(v.z, v.w));
    sts8(addr, *(uint32_t*)&h0, *(uint32_t*)&h1);
}
// 8 scaled floats -> 8 fp16 (16B)
__device__ __forceinline__ void cvt_store8s(float4 va, float4 vb, float sc, uint32_t addr) {
    va.x *= sc; va.y *= sc; va.z *= sc; va.w *= sc;
    vb.x *= sc; vb.y *= sc; vb.z *= sc; vb.w *= sc;
    __half2 h0 = __float22half2_rn(make_float2(va.x, va.y));
    __half2 h1 = __float22half2_rn(make_float2(va.z, va.w));
    __half2 h2 = __float22half2_rn(make_float2(vb.x, vb.y));
    __half2 h3 = __float22half2_rn(make_float2(vb.z, vb.w));
    sts16(addr, make_uint4(*(uint32_t*)&h0, *(uint32_t*)&h1, *(uint32_t*)&h2, *(uint32_t*)&h3));
}
// 8 fp16 -> fp32-scale -> 8 fp16 (16B)
__device__ __forceinline__ void cvtH8s(uint4 hv, float sc, uint32_t addr) {
    __half2* hp = (__half2*)&hv;
    float2 f0 = __half22float2(hp[0]);
    float2 f1 = __half22float2(hp[1]);
    float2 f2 = __half22float2(hp[2]);
    float2 f3 = __half22float2(hp[3]);
    __half2 h0 = __float22half2_rn(make_float2(f0.x * sc, f0.y * sc));
    __half2 h1 = __float22half2_rn(make_float2(f1.x * sc, f1.y * sc));
    __half2 h2 = __float22half2_rn(make_float2(f2.x * sc, f2.y * sc));
    __half2 h3 = __float22half2_rn(make_float2(f3.x * sc, f3.y * sc));
    sts16(addr, make_uint4(*(uint32_t*)&h0, *(uint32_t*)&h1, *(uint32_t*)&h2, *(uint32_t*)&h3));
}

// ---------------- softmax ----------------
__global__ void softmax_kernel(const float* __restrict__ t1,
                               const float* __restrict__ t2,
                               const float* __restrict__ t3) {
    const float* src = (blockIdx.x == 0) ? t1 : (blockIdx.x == 1) ? t2 : t3;
    float* dst = (blockIdx.x == 0) ? g_c1 : (blockIdx.x == 1) ? g_c2 : g_c3;
    int l = threadIdx.x;
    float v[16];
    float mx = -1e30f;
#pragma unroll
    for (int k = 0; k < 16; k++) { v[k] = src[l*16 + k]; mx = fmaxf(mx, v[k]); }
    float s = 0.f;
#pragma unroll
    for (int k = 0; k < 16; k++) { v[k] = expf(v[k] - mx); s += v[k]; }
    float inv = 1.f / s;
#pragma unroll
    for (int k = 0; k < 16; k++) dst[l*16 + k] = v[k] * inv;
}

// ---------------- Gram v2: 64 cols/block, 4 k1 per thread ----------------
__global__ void gram_kernel(const float* __restrict__ Wg,
                            const float* __restrict__ Wu,
                            const float* __restrict__ Wd) {
    int w = blockIdx.y;
    const float* W; float* G; int R, C;
    if (w == 0)      { W = Wg; G = g_Gg; R = Dd; C = Ff; }
    else if (w == 1) { W = Wu; G = g_Gu; R = Dd; C = Ff; }
    else             { W = Wd; G = g_Gd; R = Ff; C = Dd; }
    int c0 = blockIdx.x * 64;
    if (c0 >= C) return;

    __shared__ __align__(16) float s[16][8][64];   // 32KB
    int t = threadIdx.x;
    int cc = t & 63;
    int pg = t >> 6;          // 0..3, owns k1 in pg*4..pg*4+3
    float acc[64];
#pragma unroll
    for (int i = 0; i < 64; i++) acc[i] = 0.f;

    for (int r0 = 0; r0 < R; r0 += 8) {
        __syncthreads();
#pragma unroll
        for (int j = 0; j < 32; j++) {
            int idx = j * 256 + t;
            int lc = idx & 63, rr = (idx >> 6) & 7, k = idx >> 9;
            s[k][rr][lc] = W[(size_t)k * R * C + (size_t)(r0 + rr) * C + c0 + lc];
        }
        __syncthreads();
#pragma unroll
        for (int rr = 0; rr < 8; rr++) {
            float wv[16];
#pragma unroll
            for (int k = 0; k < 16; k++) wv[k] = s[k][rr][cc];
            float a[4];
#pragma unroll
            for (int i = 0; i < 4; i++) a[i] = s[pg * 4 + i][rr][cc];
#pragma unroll
            for (int i = 0; i < 4; i++)
#pragma unroll
                for (int k2 = 0; k2 < 16; k2++)
                    acc[i * 16 + k2] += a[i] * wv[k2];
        }
    }
#pragma unroll
    for (int i = 0; i < 4; i++)
#pragma unroll
        for (int k2 = 0; k2 < 16; k2++) {
            int p = (pg * 4 + i) * 16 + k2;
            G[(size_t)p * C + c0 + cc] = acc[i * 16 + k2];
        }
}

// ---------------- inverse norms: 8 tokens per block ----------------
__global__ void norm_kernel() {
    int w = blockIdx.z;
    int l0 = blockIdx.y * 8;
    const float* G; const float* coef; float* out; int C;
    if (w == 0)      { G = g_Gg; coef = g_c1; out = g_ing; C = Ff; }
    else if (w == 1) { G = g_Gu; coef = g_c2; out = g_inu; C = Ff; }
    else             { G = g_Gd; coef = g_c3; out = g_ind; C = Dd; }
    int c = blockIdx.x * 128 + threadIdx.x;
    if (c >= C) return;

    __shared__ float w2[8][256];
#pragma unroll
    for (int i = 0; i < 16; i++) {
        int idx = threadIdx.x * 16 + i;
        int li = idx >> 8, p = idx & 255;
        w2[li][p] = coef[(l0 + li) * 16 + (p >> 4)] * coef[(l0 + li) * 16 + (p & 15)];
    }
    __syncthreads();

    float acc[8];
#pragma unroll
    for (int i = 0; i < 8; i++) acc[i] = 0.f;
#pragma unroll 4
    for (int p = 0; p < 256; p++) {
        float g = G[(size_t)p * C + c];
#pragma unroll
        for (int i = 0; i < 8; i++) acc[i] += w2[i][p] * g;
    }
#pragma unroll
    for (int i = 0; i < 8; i++)
        out[(l0 + i) * C + c] = 1.f / fmaxf(sqrtf(fmaxf(acc[i], 0.f)), 1e-12f);
}

// ---------------- UV GEMM: persistent x in smem, B-only double-buffered staging ----------------
// A_eff = coef-scaled x; coef applied to A fragments in registers (HMUL2).
__global__ void __launch_bounds__(512, 1) gemm13(
    const float* __restrict__ x,
    const float* __restrict__ Bw0, const float* __restrict__ Bw1)
{
    constexpr int BN = 256, WN = 64, NF = 8;
    constexpr int XSTRIDE = 1040;            // 512 fp16 + 16B pad (65*16, conflict-free)
    constexpr int XMB = 128 * XSTRIDE;       // 133120
    constexpr int BSTRIDE = 528;
    constexpr int BMB = 32 * BSTRIDE;        // 16896
    constexpr int NIT = 256;                 // 8192 / 32

    extern __shared__ __align__(128) char dynsmem[];
    uint32_t xT = smem_u32(dynsmem);
    uint32_t bB = xT + XMB;

    const float* coef; float* Cout; const float* Bw;
    if (blockIdx.z == 0) { coef = g_c1; Bw = Bw0; Cout = g_U; }
    else                 { coef = g_c2; Bw = Bw1; Cout = g_V; }

    int t = threadIdx.x, lane = t & 31, warp = t >> 5;
    int wm = warp & 3, wn = warp >> 2;
    int m0 = blockIdx.y * 128, n0 = blockIdx.x * BN;

    // ---- prologue: x tile -> smem fp16 (unscaled) ----
    {
        int row = t >> 2, aq = t & 3;
        const float* xr = x + (size_t)(m0 + row) * 512 + aq * 128;
        uint32_t dst = xT + (uint32_t)row * XSTRIDE + aq * 256;
#pragma unroll
        for (int j = 0; j < 16; j++) {
            float4 a = *(const float4*)(xr + j * 8);
            float4 b = *(const float4*)(xr + j * 8 + 4);
            cvt_store8s(a, b, 1.0f, dst + j * 16);
        }
    }

    // B staging coords
    int krow = t >> 4, bq = t & 15;
    const float* bRowBase = Bw + (size_t)krow * 1024 + n0;
    uint32_t bRowOff = (uint32_t)krow * BSTRIDE;

    float acc[2][NF][4];
#pragma unroll
    for (int f = 0; f < 2; f++)
#pragma unroll
        for (int g = 0; g < NF; g++)
#pragma unroll
            for (int j = 0; j < 4; j++) acc[f][g][j] = 0.f;

    // stage iter-0 B
    float4 pbv[4];
#pragma unroll
    for (int j = 0; j < 4; j++)
        pbv[j] = *(const float4*)(bRowBase + (bq + 16 * j) * 4);
#pragma unroll
    for (int j = 0; j < 4; j++)
        cvt_store4(pbv[j], bB + bRowOff + (bq + 16 * j) * 8);
    __syncthreads();

    // per-fragment coef registers (half2 broadcast), updated per k-segment
    uint32_t chLo[2], chHi[2];
    int rbase = wm * 32 + (lane >> 2);

    for (int it = 0; it < NIT; it++) {
        int kt = it << 5;
        uint32_t cur = bB + (uint32_t)(it & 1) * BMB;
        uint32_t nxt = bB + (uint32_t)((it + 1) & 1) * BMB;
        bool more = (it + 1 < NIT);

        if ((kt & 511) == 0) {
            int kseg = kt >> 9;
#pragma unroll
            for (int f = 0; f < 2; f++) {
                float cl = coef[(rbase + f * 16) * 16 + kseg];
                float ch = coef[(rbase + f * 16 + 8) * 16 + kseg];
                __half2 hl = __half2half2(__float2half_rn(cl));
                __half2 hh = __half2half2(__float2half_rn(ch));
                chLo[f] = *(uint32_t*)&hl;
                chHi[f] = *(uint32_t*)&hh;
            }
        }

        if (more) {
            int ktn = (it + 1) << 5;
            const float* br = bRowBase + (size_t)ktn * 1024;
#pragma unroll
            for (int j = 0; j < 4; j++)
                pbv[j] = *(const float4*)(br + (bq + 16 * j) * 4);
        }

        // ---- MMA from persistent x + cur B ----
#pragma unroll
        for (int ks = 0; ks < 2; ks++) {
            uint32_t BF[NF][2];
            uint32_t brow = (uint32_t)(ks * 16 + (lane & 15)) * BSTRIDE;
#pragma unroll
            for (int j = 0; j < NF / 2; j++) {
                uint32_t coff = (uint32_t)(wn * WN + j * 16 + ((lane >> 4) & 1) * 8) * 2;
                uint32_t r[4];
                ldsm4t(r, cur + brow + coff);
                BF[2*j][0] = r[0]; BF[2*j][1] = r[1];
                BF[2*j+1][0] = r[2]; BF[2*j+1][1] = r[3];
            }
            uint32_t acol = ((uint32_t)(kt & 511) << 1) + ks * 32 + ((lane >> 4) & 1) * 16;
            uint32_t AF[2][4];
#pragma unroll
            for (int f = 0; f < 2; f++) {
                uint32_t roff = (uint32_t)(wm * 32 + f * 16 + (lane & 15)) * XSTRIDE + acol;
                ldsm4(AF[f], xT + roff);
                AF[f][0] = hmul2u(AF[f][0], chLo[f]);
                AF[f][2] = hmul2u(AF[f][2], chLo[f]);
                AF[f][1] = hmul2u(AF[f][1], chHi[f]);
                AF[f][3] = hmul2u(AF[f][3], chHi[f]);
            }
#pragma unroll
            for (int f = 0; f < 2; f++)
#pragma unroll
                for (int g = 0; g < NF; g++)
                    mmaf16(acc[f][g], AF[f], BF[g]);
        }

        if (more) {
#pragma unroll
            for (int j = 0; j < 4; j++)
                cvt_store4(pbv[j], nxt + bRowOff + (bq + 16 * j) * 8);
        }
        __syncthreads();
    }

#pragma unroll
    for (int f = 0; f < 2; f++) {
#pragma unroll
        for (int g = 0; g < NF; g++) {
            int r0 = m0 + wm * 32 + f * 16 + (lane >> 2);
            int col = n0 + wn * WN + g * 8 + (lane & 3) * 2;
            float* p = Cout + (size_t)r0 * 1024 + col;
            *(float2*)p = make_float2(acc[f][g][0], acc[f][g][1]);
            *(float2*)(p + 8 * 1024) = make_float2(acc[f][g][2], acc[f][g][3]);
        }
    }
}

// ---------------- down GEMM: fp16 h input, split-K=4, double-buffered ----------------
__global__ void __launch_bounds__(512, 1) gemm14(const float* __restrict__ Bw)
{
    constexpr int BN = 256, WN = 64, NF = 8;
    constexpr int AMB = 128 * 80;
    constexpr int BSTRIDE = 528;
    constexpr int BMB = 32 * BSTRIDE;
    constexpr int STG = AMB + BMB;         // 27136
    constexpr int NG = 512;

    extern __shared__ __align__(128) char dynsmem[];
    uint32_t base = smem_u32(dynsmem);

    float* part[4] = { g_O, g_U, g_U + (size_t)Mm * Dd, g_V };
    float* Cout = part[blockIdx.z];
    int kglob0 = blockIdx.z * 4096;

    int t = threadIdx.x, lane = t & 31, warp = t >> 5;
    int wm = warp & 3, wn = warp >> 2;
    int m0 = blockIdx.y * 128, n0 = blockIdx.x * BN;

    int arow = t >> 2, aq = t & 3;
    const __half* aRowBase = ((const __half*)g_H) + (size_t)(m0 + arow) * 1024 + aq * 8;
    const float* crow = g_c3 + ((m0 + arow) & 127) * 16;
    uint32_t aoff = (uint32_t)arow * 80 + aq * 16;

    int krow = t >> 4;
    int bq = t & 15;
    const float* bRowBase = Bw + (size_t)(kglob0 + krow) * NG + n0;
    uint32_t bRowOff = (uint32_t)krow * BSTRIDE;

    float acc[2][NF][4];
#pragma unroll
    for (int f = 0; f < 2; f++)
#pragma unroll
        for (int g = 0; g < NF; g++)
#pragma unroll
            for (int j = 0; j < 4; j++) acc[f][g][j] = 0.f;

    const int nit = 128;

    uint4 pau;
    float4 pbv[4];
    float psc;
    {
        int ktg = kglob0;
        psc = crow[ktg >> 10];
        pau = *(const uint4*)(aRowBase + (ktg & 1023));
#pragma unroll
        for (int j = 0; j < 4; j++)
            pbv[j] = *(const float4*)(bRowBase + (bq + 16 * j) * 4);
        cvtH8s(pau, psc, base + aoff);
#pragma unroll
        for (int j = 0; j < 4; j++)
            cvt_store4(pbv[j], base + AMB + bRowOff + (bq + 16 * j) * 8);
    }
    __syncthreads();

    for (int it = 0; it < nit; it++) {
        uint32_t cur = base + (uint32_t)(it & 1) * STG;
        uint32_t nxt = base + (uint32_t)((it + 1) & 1) * STG;
        bool more = (it + 1 < nit);

        if (more) {
            int ktn = (it + 1) << 5;
            int ktg = kglob0 + ktn;
            psc = crow[ktg >> 10];
            pau = *(const uint4*)(aRowBase + (ktg & 1023));
            const float* br = bRowBase + (size_t)ktn * NG;
#pragma unroll
            for (int j = 0; j < 4; j++)
                pbv[j] = *(const float4*)(br + (bq + 16 * j) * 4);
        }

        uint32_t sA = cur, sB = cur + AMB;
#pragma unroll
        for (int ks = 0; ks < 2; ks++) {
            uint32_t BF[NF][2];
            uint32_t brow = (uint32_t)(ks * 16 + (lane & 15)) * BSTRIDE;
#pragma unroll
            for (int j = 0; j < NF / 2; j++) {
                uint32_t coff = (uint32_t)(wn * WN + j * 16 + ((lane >> 4) & 1) * 8) * 2;
                uint32_t r[4];
                ldsm4t(r, sB + brow + coff);
                BF[2*j][0] = r[0]; BF[2*j][1] = r[1];
                BF[2*j+1][0] = r[2]; BF[2*j+1][1] = r[3];
            }
            uint32_t acolB = (uint32_t)ks * 32 + ((lane >> 4) & 1) * 16;
            uint32_t AF[2][4];
#pragma unroll
            for (int f = 0; f < 2; f++) {
                uint32_t roff = (uint32_t)(wm * 32 + f * 16 + (lane & 15)) * 80 + acolB;
                ldsm4(AF[f], sA + roff);
            }
#pragma unroll
            for (int f = 0; f < 2; f++)
#pragma unroll
                for (int g = 0; g < NF; g++)
                    mmaf16(acc[f][g], AF[f], BF[g]);
        }

        if (more) {
            cvtH8s(pau, psc, nxt + aoff);
#pragma unroll
            for (int j = 0; j < 4; j++)
                cvt_store4(pbv[j], nxt + AMB + bRowOff + (bq + 16 * j) * 8);
        }
        __syncthreads();
    }

#pragma unroll
    for (int f = 0; f < 2; f++) {
#pragma unroll
        for (int g = 0; g < NF; g++) {
            int r0 = m0 + wm * 32 + f * 16 + (lane >> 2);
            int col = n0 + wn * WN + g * 8 + (lane & 3) * 2;
            float* p = Cout + (size_t)r0 * NG + col;
            *(float2*)p = make_float2(acc[f][g][0], acc[f][g][1]);
            *(float2*)(p + 8 * NG) = make_float2(acc[f][g][2], acc[f][g][3]);
        }
    }
}

// ---------------- elementwise h: writes fp16 ----------------
__global__ void h_kernel(const float* __restrict__ usp, const float* __restrict__ vsp) {
    const float SQRT_D = 22.62741699796952f;
    int i4 = blockIdx.x * blockDim.x + threadIdx.x;
    if (i4 >= Mm * Ff / 4) return;
    int m  = i4 >> 8;
    int f  = (i4 & 255) * 4;
    int l  = m & 127;

    float4 u  = *(const float4*)(g_U   + (size_t)m * Ff + f);
    float4 v  = *(const float4*)(g_V   + (size_t)m * Ff + f);
    float4 ig = *(const float4*)(g_ing + (size_t)l * Ff + f);
    float4 iu = *(const float4*)(g_inu + (size_t)l * Ff + f);
    float4 us = *(const float4*)(usp + f);
    float4 vs = *(const float4*)(vsp + f);

    float4 h;
    { float uu = u.x * ig.x, vv = v.x * iu.x; float zz = fabsf(vs.x) * SQRT_D * vv;
      h.x = (zz / (1.f + expf(-zz))) * (fabsf(us.x) * uu); }
    { float uu = u.y * ig.y, vv = v.y * iu.y; float zz = fabsf(vs.y) * SQRT_D * vv;
      h.y = (zz / (1.f + expf(-zz))) * (fabsf(us.y) * uu); }
    { float uu = u.z * ig.z, vv = v.z * iu.z; float zz = fabsf(vs.z) * SQRT_D * vv;
      h.z = (zz / (1.f + expf(-zz))) * (fabsf(us.z) * uu); }
    { float uu = u.w * ig.w, vv = v.w * iu.w; float zz = fabsf(vs.w) * SQRT_D * vv;
      h.w = (zz / (1.f + expf(-zz))) * (fabsf(us.w) * uu); }

    __half2 o0 = __float22half2_rn(make_float2(h.x, h.y));
    __half2 o1 = __float22half2_rn(make_float2(h.z, h.w));
    *(uint2*)(((__half*)g_H) + (size_t)m * Ff + f) =
        make_uint2(*(uint32_t*)&o0, *(uint32_t*)&o1);
}

// ---------------- final: sum 4 split-K partials, apply down-norm, row L2 normalize ----------------
__global__ void out_kernel(float* __restrict__ out) {
    int m = blockIdx.x;
    int t = threadIdx.x;
    int l = m & 127;

    size_t off = (size_t)m * Dd + t * 4;
    float4 p0 = *(const float4*)(g_O + off);
    float4 p1 = *(const float4*)(g_U + off);
    float4 p2 = *(const float4*)(g_U + (size_t)Mm * Dd + off);
    float4 p3 = *(const float4*)(g_V + off);
    float4 iv = *(const float4*)(g_ind + (size_t)l * Dd + t * 4);

    float4 o;
    o.x = ((p0.x + p1.x) + (p2.x + p3.x)) * iv.x;
    o.y = ((p0.y + p1.y) + (p2.y + p3.y)) * iv.y;
    o.z = ((p0.z + p1.z) + (p2.z + p3.z)) * iv.z;
    o.w = ((p0.w + p1.w) + (p2.w + p3.w)) * iv.w;

    float ss = o.x*o.x + o.y*o.y + o.z*o.z + o.w*o.w;
#pragma unroll
    for (int offm = 16; offm > 0; offm >>= 1)
        ss += __shfl_xor_sync(0xffffffffu, ss, offm);

    __shared__ float ws[4];
    if ((t & 31) == 0) ws[t >> 5] = ss;
    __syncthreads();
    float tot = ws[0] + ws[1] + ws[2] + ws[3];
    float sc = 1.f / fmaxf(sqrtf(tot), 1e-12f);

    o.x *= sc; o.y *= sc; o.z *= sc; o.w *= sc;
    *(float4*)(out + off) = o;
}

// ---------------- launch ----------------
extern "C" void kernel_launch(void* const* d_in, const int* in_sizes, int n_in,
                              void* d_out, int out_size) {
    const float* x   = (const float*)d_in[0];
    const float* Wg  = (const float*)d_in[1];
    const float* Wu  = (const float*)d_in[2];
    const float* Wd  = (const float*)d_in[3];
    const float* t1  = (const float*)d_in[4];
    const float* t2  = (const float*)d_in[5];
    const float* t3  = (const float*)d_in[6];
    const float* usp = (const float*)d_in[7];
    const float* vsp = (const float*)d_in[8];
    float* out = (float*)d_out;

    const int DSMEM_UV = 128 * 1040 + 2 * 32 * 528;   // 166912
    const int DSMEM_DN = 2 * (128 * 80 + 32 * 528);   // 54272
    cudaFuncSetAttribute(gemm13, cudaFuncAttributeMaxDynamicSharedMemorySize, DSMEM_UV);
    cudaFuncSetAttribute(gemm14, cudaFuncAttributeMaxDynamicSharedMemorySize, DSMEM_DN);

    softmax_kernel<<<3, 128>>>(t1, t2, t3);
    gram_kernel<<<dim3(16, 3), 256>>>(Wg, Wu, Wd);
    norm_kernel<<<dim3(8, 16, 3), 128>>>();

    // U and V fused (z=0 -> U, z=1 -> V): persistent-x, BN=256, 128 blocks
    gemm13<<<dim3(4, 16, 2), 512, DSMEM_UV>>>(x, Wg, Wu);
    // h = silu(vs*v) * (us*u), stored fp16
    h_kernel<<<2048, 256>>>(usp, vsp);
    // O partials: split-K=4 -> g_O, g_U, g_U+1M, g_V
    gemm14<<<dim3(2, 16, 4), 512, DSMEM_DN>>>(Wd);
    // final: sum 4 partials + normalize
    out_kernel<<<2048, 128>>>(out);
}

// round 17
// speedup vs baseline: 1.2722x; 1.2722x over previous
#include <cuda_runtime.h>
#include <cuda_fp16.h>
#include <math.h>
#include <stdint.h>

// Problem constants
#define Bb 16
#define Ll 128
#define Dd 512
#define Ff 1024
#define Mm 2048

// -------- device scratch (proven safe footprint) --------
__device__ __align__(16) float g_c1[Ll*16];
__device__ __align__(16) float g_c2[Ll*16];
__device__ __align__(16) float g_c3[Ll*16];
__device__ __align__(16) float g_Gg[256*Ff];
__device__ __align__(16) float g_Gu[256*Ff];
__device__ __align__(16) float g_Gd[256*Dd];
__device__ __align__(16) float g_ing[Ll*Ff];
__device__ __align__(16) float g_inu[Ll*Ff];
__device__ __align__(16) float g_ind[Ll*Dd];
__device__ __align__(16) float g_U[Mm*Ff];   // reused: split-K partials 1,2 for O
__device__ __align__(16) float g_V[Mm*Ff];   // reused: split-K partial 3 for O
__device__ __align__(16) float g_H[Mm*Ff];   // h fp16 in first half; 2nd half = gram scratch
__device__ __align__(16) float g_O[Mm*Dd];   // split-K partial 0

// ---------------- PTX helpers ----------------
__device__ __forceinline__ uint32_t smem_u32(const void* p) {
    uint32_t a;
    asm("{ .reg .u64 t; cvta.to.shared.u64 t, %1; cvt.u32.u64 %0, t; }" : "=r"(a) : "l"(p));
    return a;
}
__device__ __forceinline__ void ldsm4(uint32_t* r, uint32_t addr) {
    asm volatile("ldmatrix.sync.aligned.m8n8.x4.shared.b16 {%0,%1,%2,%3}, [%4];"
        : "=r"(r[0]), "=r"(r[1]), "=r"(r[2]), "=r"(r[3]) : "r"(addr));
}
__device__ __forceinline__ void ldsm4t(uint32_t* r, uint32_t addr) {
    asm volatile("ldmatrix.sync.aligned.m8n8.x4.trans.shared.b16 {%0,%1,%2,%3}, [%4];"
        : "=r"(r[0]), "=r"(r[1]), "=r"(r[2]), "=r"(r[3]) : "r"(addr));
}
__device__ __forceinline__ void mmaf16(float* c, const uint32_t* a, const uint32_t* b) {
    asm volatile("mma.sync.aligned.m16n8k16.row.col.f32.f16.f16.f32 "
        "{%0,%1,%2,%3}, {%4,%5,%6,%7}, {%8,%9}, {%0,%1,%2,%3};"
        : "+f"(c[0]), "+f"(c[1]), "+f"(c[2]), "+f"(c[3])
        : "r"(a[0]), "r"(a[1]), "r"(a[2]), "r"(a[3]), "r"(b[0]), "r"(b[1]));
}
__device__ __forceinline__ void sts16(uint32_t addr, uint4 v) {
    asm volatile("st.shared.v4.b32 [%0], {%1,%2,%3,%4};" ::
        "r"(addr), "r"(v.x), "r"(v.y), "r"(v.z), "r"(v.w) : "memory");
}
__device__ __forceinline__ void sts8(uint32_t addr, uint32_t x, uint32_t y) {
    asm volatile("st.shared.v2.b32 [%0], {%1,%2};" :: "r"(addr), "r"(x), "r"(y) : "memory");
}
__device__ __forceinline__ uint32_t hmul2u(uint32_t a, uint32_t b) {
    __half2 r = __hmul2(*(__half2*)&a, *(__half2*)&b);
    return *(uint32_t*)&r;
}

// float4 -> 4 fp16 (8B)
__device__ __forceinline__ void cvt_store4(float4 v, uint32_t addr) {
    __half2 h0 = __float22half2_rn(make_float2(v.x, v.y));
    __half2 h1 = __float22half2_rn(make_float2(v.z, v.w));
    sts8(addr, *(uint32_t*)&h0, *(uint32_t*)&h1);
}
// 8 scaled floats -> 8 fp16 (16B)
__device__ __forceinline__ void cvt_store8s(float4 va, float4 vb, float sc, uint32_t addr) {
    va.x *= sc; va.y *= sc; va.z *= sc; va.w *= sc;
    vb.x *= sc; vb.y *= sc; vb.z *= sc; vb.w *= sc;
    __half2 h0 = __float22half2_rn(make_float2(va.x, va.y));
    __half2 h1 = __float22half2_rn(make_float2(va.z, va.w));
    __half2 h2 = __float22half2_rn(make_float2(vb.x, vb.y));
    __half2 h3 = __float22half2_rn(make_float2(vb.z, vb.w));
    sts16(addr, make_uint4(*(uint32_t*)&h0, *(uint32_t*)&h1, *(uint32_t*)&h2, *(uint32_t*)&h3));
}
// 8 fp16 -> fp32-scale -> 8 fp16 (16B)
__device__ __forceinline__ void cvtH8s(uint4 hv, float sc, uint32_t addr) {
    __half2* hp = (__half2*)&hv;
    float2 f0 = __half22float2(hp[0]);
    float2 f1 = __half22float2(hp[1]);
    float2 f2 = __half22float2(hp[2]);
    float2 f3 = __half22float2(hp[3]);
    __half2 h0 = __float22half2_rn(make_float2(f0.x * sc, f0.y * sc));
    __half2 h1 = __float22half2_rn(make_float2(f1.x * sc, f1.y * sc));
    __half2 h2 = __float22half2_rn(make_float2(f2.x * sc, f2.y * sc));
    __half2 h3 = __float22half2_rn(make_float2(f3.x * sc, f3.y * sc));
    sts16(addr, make_uint4(*(uint32_t*)&h0, *(uint32_t*)&h1, *(uint32_t*)&h2, *(uint32_t*)&h3));
}

// ---------------- softmax ----------------
__global__ void softmax_kernel(const float* __restrict__ t1,
                               const float* __restrict__ t2,
                               const float* __restrict__ t3) {
    const float* src = (blockIdx.x == 0) ? t1 : (blockIdx.x == 1) ? t2 : t3;
    float* dst = (blockIdx.x == 0) ? g_c1 : (blockIdx.x == 1) ? g_c2 : g_c3;
    int l = threadIdx.x;
    float v[16];
    float mx = -1e30f;
#pragma unroll
    for (int k = 0; k < 16; k++) { v[k] = src[l*16 + k]; mx = fmaxf(mx, v[k]); }
    float s = 0.f;
#pragma unroll
    for (int k = 0; k < 16; k++) { v[k] = expf(v[k] - mx); s += v[k]; }
    float inv = 1.f / s;
#pragma unroll
    for (int k = 0; k < 16; k++) dst[l*16 + k] = v[k] * inv;
}

// ---------------- Gram v1 (proven) + down plane split over R into 2 halves ----------------
// plane 0: gate (R=512), 1: up (R=512), 2: down rows [0,512), 3: down rows [512,1024)
__global__ void gram_kernel(const float* __restrict__ Wg,
                            const float* __restrict__ Wu,
                            const float* __restrict__ Wd) {
    int w = blockIdx.y;
    const float* W; float* G; int R, C, rlo, rhi;
    if (w == 0)      { W = Wg; G = g_Gg; R = Dd; C = Ff; rlo = 0;   rhi = 512; }
    else if (w == 1) { W = Wu; G = g_Gu; R = Dd; C = Ff; rlo = 0;   rhi = 512; }
    else if (w == 2) { W = Wd; G = g_Gd; R = Ff; C = Dd; rlo = 0;   rhi = 512; }
    else             { W = Wd; G = g_H + (size_t)1024 * 1024; R = Ff; C = Dd; rlo = 512; rhi = 1024; }
    int c0 = blockIdx.x * 32;
    if (c0 >= C) return;

    __shared__ __align__(16) float s[16][8][32];
    int t = threadIdx.x;
    int cc = t & 31;
    int pg = t >> 5;
    float acc[32];
#pragma unroll
    for (int i = 0; i < 32; i++) acc[i] = 0.f;

    for (int r0 = rlo; r0 < rhi; r0 += 8) {
        __syncthreads();
#pragma unroll
        for (int j = 0; j < 16; j++) {
            int idx = j * 256 + t;
            int lc = idx & 31, rr = (idx >> 5) & 7, k = idx >> 8;
            s[k][rr][lc] = W[(size_t)k * R * C + (size_t)(r0 + rr) * C + c0 + lc];
        }
        __syncthreads();
#pragma unroll
        for (int rr = 0; rr < 8; rr++) {
            float wv[16];
#pragma unroll
            for (int k = 0; k < 16; k++) wv[k] = s[k][rr][cc];
            float a0 = s[(pg << 1) + 0][rr][cc];
            float a1 = s[(pg << 1) + 1][rr][cc];
#pragma unroll
            for (int pp = 0; pp < 16; pp++) acc[pp]      += a0 * wv[pp];
#pragma unroll
            for (int pp = 0; pp < 16; pp++) acc[16 + pp] += a1 * wv[pp];
        }
    }
#pragma unroll
    for (int pp = 0; pp < 32; pp++) {
        int p = ((pg << 1) + (pp >> 4)) * 16 + (pp & 15);
        G[(size_t)p * C + c0 + cc] = acc[pp];
    }
}

// ---------------- inverse norms: 8 tokens per block; down plane sums 2 partials ----------------
__global__ void norm_kernel() {
    int w = blockIdx.z;
    int l0 = blockIdx.y * 8;
    const float* G; const float* coef; float* out; int C;
    const float* G2 = nullptr;
    if (w == 0)      { G = g_Gg; coef = g_c1; out = g_ing; C = Ff; }
    else if (w == 1) { G = g_Gu; coef = g_c2; out = g_inu; C = Ff; }
    else             { G = g_Gd; coef = g_c3; out = g_ind; C = Dd;
                       G2 = g_H + (size_t)1024 * 1024; }
    int c = blockIdx.x * 128 + threadIdx.x;
    if (c >= C) return;

    __shared__ float w2[8][256];
#pragma unroll
    for (int i = 0; i < 16; i++) {
        int idx = threadIdx.x * 16 + i;
        int li = idx >> 8, p = idx & 255;
        w2[li][p] = coef[(l0 + li) * 16 + (p >> 4)] * coef[(l0 + li) * 16 + (p & 15)];
    }
    __syncthreads();

    float acc[8];
#pragma unroll
    for (int i = 0; i < 8; i++) acc[i] = 0.f;
#pragma unroll 4
    for (int p = 0; p < 256; p++) {
        float g = G[(size_t)p * C + c];
        if (w == 2) g += G2[(size_t)p * C + c];
#pragma unroll
        for (int i = 0; i < 8; i++) acc[i] += w2[i][p] * g;
    }
#pragma unroll
    for (int i = 0; i < 8; i++)
        out[(l0 + i) * C + c] = 1.f / fmaxf(sqrtf(fmaxf(acc[i], 0.f)), 1e-12f);
}

// ---------------- UV GEMM: persistent x in smem, B double-buffered (R16-proven) ----------------
__global__ void __launch_bounds__(512, 1) gemm13(
    const float* __restrict__ x,
    const float* __restrict__ Bw0, const float* __restrict__ Bw1)
{
    constexpr int BN = 256, WN = 64, NF = 8;
    constexpr int XSTRIDE = 1040;
    constexpr int XMB = 128 * XSTRIDE;
    constexpr int BSTRIDE = 528;
    constexpr int BMB = 32 * BSTRIDE;
    constexpr int NIT = 256;

    extern __shared__ __align__(128) char dynsmem[];
    uint32_t xT = smem_u32(dynsmem);
    uint32_t bB = xT + XMB;

    const float* coef; float* Cout; const float* Bw;
    if (blockIdx.z == 0) { coef = g_c1; Bw = Bw0; Cout = g_U; }
    else                 { coef = g_c2; Bw = Bw1; Cout = g_V; }

    int t = threadIdx.x, lane = t & 31, warp = t >> 5;
    int wm = warp & 3, wn = warp >> 2;
    int m0 = blockIdx.y * 128, n0 = blockIdx.x * BN;

    {
        int row = t >> 2, aq = t & 3;
        const float* xr = x + (size_t)(m0 + row) * 512 + aq * 128;
        uint32_t dst = xT + (uint32_t)row * XSTRIDE + aq * 256;
#pragma unroll
        for (int j = 0; j < 16; j++) {
            float4 a = *(const float4*)(xr + j * 8);
            float4 b = *(const float4*)(xr + j * 8 + 4);
            cvt_store8s(a, b, 1.0f, dst + j * 16);
        }
    }

    int krow = t >> 4, bq = t & 15;
    const float* bRowBase = Bw + (size_t)krow * 1024 + n0;
    uint32_t bRowOff = (uint32_t)krow * BSTRIDE;

    float acc[2][NF][4];
#pragma unroll
    for (int f = 0; f < 2; f++)
#pragma unroll
        for (int g = 0; g < NF; g++)
#pragma unroll
            for (int j = 0; j < 4; j++) acc[f][g][j] = 0.f;

    float4 pbv[4];
#pragma unroll
    for (int j = 0; j < 4; j++)
        pbv[j] = *(const float4*)(bRowBase + (bq + 16 * j) * 4);
#pragma unroll
    for (int j = 0; j < 4; j++)
        cvt_store4(pbv[j], bB + bRowOff + (bq + 16 * j) * 8);
    __syncthreads();

    uint32_t chLo[2], chHi[2];
    int rbase = wm * 32 + (lane >> 2);

    for (int it = 0; it < NIT; it++) {
        int kt = it << 5;
        uint32_t cur = bB + (uint32_t)(it & 1) * BMB;
        uint32_t nxt = bB + (uint32_t)((it + 1) & 1) * BMB;
        bool more = (it + 1 < NIT);

        if ((kt & 511) == 0) {
            int kseg = kt >> 9;
#pragma unroll
            for (int f = 0; f < 2; f++) {
                float cl = coef[(rbase + f * 16) * 16 + kseg];
                float ch = coef[(rbase + f * 16 + 8) * 16 + kseg];
                __half2 hl = __half2half2(__float2half_rn(cl));
                __half2 hh = __half2half2(__float2half_rn(ch));
                chLo[f] = *(uint32_t*)&hl;
                chHi[f] = *(uint32_t*)&hh;
            }
        }

        if (more) {
            int ktn = (it + 1) << 5;
            const float* br = bRowBase + (size_t)ktn * 1024;
#pragma unroll
            for (int j = 0; j < 4; j++)
                pbv[j] = *(const float4*)(br + (bq + 16 * j) * 4);
        }

#pragma unroll
        for (int ks = 0; ks < 2; ks++) {
            uint32_t BF[NF][2];
            uint32_t brow = (uint32_t)(ks * 16 + (lane & 15)) * BSTRIDE;
#pragma unroll
            for (int j = 0; j < NF / 2; j++) {
                uint32_t coff = (uint32_t)(wn * WN + j * 16 + ((lane >> 4) & 1) * 8) * 2;
                uint32_t r[4];
                ldsm4t(r, cur + brow + coff);
                BF[2*j][0] = r[0]; BF[2*j][1] = r[1];
                BF[2*j+1][0] = r[2]; BF[2*j+1][1] = r[3];
            }
            uint32_t acol = ((uint32_t)(kt & 511) << 1) + ks * 32 + ((lane >> 4) & 1) * 16;
            uint32_t AF[2][4];
#pragma unroll
            for (int f = 0; f < 2; f++) {
                uint32_t roff = (uint32_t)(wm * 32 + f * 16 + (lane & 15)) * XSTRIDE + acol;
                ldsm4(AF[f], xT + roff);
                AF[f][0] = hmul2u(AF[f][0], chLo[f]);
                AF[f][2] = hmul2u(AF[f][2], chLo[f]);
                AF[f][1] = hmul2u(AF[f][1], chHi[f]);
                AF[f][3] = hmul2u(AF[f][3], chHi[f]);
            }
#pragma unroll
            for (int f = 0; f < 2; f++)
#pragma unroll
                for (int g = 0; g < NF; g++)
                    mmaf16(acc[f][g], AF[f], BF[g]);
        }

        if (more) {
#pragma unroll
            for (int j = 0; j < 4; j++)
                cvt_store4(pbv[j], nxt + bRowOff + (bq + 16 * j) * 8);
        }
        __syncthreads();
    }

#pragma unroll
    for (int f = 0; f < 2; f++) {
#pragma unroll
        for (int g = 0; g < NF; g++) {
            int r0 = m0 + wm * 32 + f * 16 + (lane >> 2);
            int col = n0 + wn * WN + g * 8 + (lane & 3) * 2;
            float* p = Cout + (size_t)r0 * 1024 + col;
            *(float2*)p = make_float2(acc[f][g][0], acc[f][g][1]);
            *(float2*)(p + 8 * 1024) = make_float2(acc[f][g][2], acc[f][g][3]);
        }
    }
}

// ---------------- down GEMM: fp16 h input, split-K=4, double-buffered (R16-proven) ----------------
__global__ void __launch_bounds__(512, 1) gemm14(const float* __restrict__ Bw)
{
    constexpr int BN = 256, WN = 64, NF = 8;
    constexpr int AMB = 128 * 80;
    constexpr int BSTRIDE = 528;
    constexpr int BMB = 32 * BSTRIDE;
    constexpr int STG = AMB + BMB;
    constexpr int NG = 512;

    extern __shared__ __align__(128) char dynsmem[];
    uint32_t base = smem_u32(dynsmem);

    float* part[4] = { g_O, g_U, g_U + (size_t)Mm * Dd, g_V };
    float* Cout = part[blockIdx.z];
    int kglob0 = blockIdx.z * 4096;

    int t = threadIdx.x, lane = t & 31, warp = t >> 5;
    int wm = warp & 3, wn = warp >> 2;
    int m0 = blockIdx.y * 128, n0 = blockIdx.x * BN;

    int arow = t >> 2, aq = t & 3;
    const __half* aRowBase = ((const __half*)g_H) + (size_t)(m0 + arow) * 1024 + aq * 8;
    const float* crow = g_c3 + ((m0 + arow) & 127) * 16;
    uint32_t aoff = (uint32_t)arow * 80 + aq * 16;

    int krow = t >> 4;
    int bq = t & 15;
    const float* bRowBase = Bw + (size_t)(kglob0 + krow) * NG + n0;
    uint32_t bRowOff = (uint32_t)krow * BSTRIDE;

    float acc[2][NF][4];
#pragma unroll
    for (int f = 0; f < 2; f++)
#pragma unroll
        for (int g = 0; g < NF; g++)
#pragma unroll
            for (int j = 0; j < 4; j++) acc[f][g][j] = 0.f;

    const int nit = 128;

    uint4 pau;
    float4 pbv[4];
    float psc;
    {
        int ktg = kglob0;
        psc = crow[ktg >> 10];
        pau = *(const uint4*)(aRowBase + (ktg & 1023));
#pragma unroll
        for (int j = 0; j < 4; j++)
            pbv[j] = *(const float4*)(bRowBase + (bq + 16 * j) * 4);
        cvtH8s(pau, psc, base + aoff);
#pragma unroll
        for (int j = 0; j < 4; j++)
            cvt_store4(pbv[j], base + AMB + bRowOff + (bq + 16 * j) * 8);
    }
    __syncthreads();

    for (int it = 0; it < nit; it++) {
        uint32_t cur = base + (uint32_t)(it & 1) * STG;
        uint32_t nxt = base + (uint32_t)((it + 1) & 1) * STG;
        bool more = (it + 1 < nit);

        if (more) {
            int ktn = (it + 1) << 5;
            int ktg = kglob0 + ktn;
            psc = crow[ktg >> 10];
            pau = *(const uint4*)(aRowBase + (ktg & 1023));
            const float* br = bRowBase + (size_t)ktn * NG;
#pragma unroll
            for (int j = 0; j < 4; j++)
                pbv[j] = *(const float4*)(br + (bq + 16 * j) * 4);
        }

        uint32_t sA = cur, sB = cur + AMB;
#pragma unroll
        for (int ks = 0; ks < 2; ks++) {
            uint32_t BF[NF][2];
            uint32_t brow = (uint32_t)(ks * 16 + (lane & 15)) * BSTRIDE;
#pragma unroll
            for (int j = 0; j < NF / 2; j++) {
                uint32_t coff = (uint32_t)(wn * WN + j * 16 + ((lane >> 4) & 1) * 8) * 2;
                uint32_t r[4];
                ldsm4t(r, sB + brow + coff);
                BF[2*j][0] = r[0]; BF[2*j][1] = r[1];
                BF[2*j+1][0] = r[2]; BF[2*j+1][1] = r[3];
            }
            uint32_t acolB = (uint32_t)ks * 32 + ((lane >> 4) & 1) * 16;
            uint32_t AF[2][4];
#pragma unroll
            for (int f = 0; f < 2; f++) {
                uint32_t roff = (uint32_t)(wm * 32 + f * 16 + (lane & 15)) * 80 + acolB;
                ldsm4(AF[f], sA + roff);
            }
#pragma unroll
            for (int f = 0; f < 2; f++)
#pragma unroll
                for (int g = 0; g < NF; g++)
                    mmaf16(acc[f][g], AF[f], BF[g]);
        }

        if (more) {
            cvtH8s(pau, psc, nxt + aoff);
#pragma unroll
            for (int j = 0; j < 4; j++)
                cvt_store4(pbv[j], nxt + AMB + bRowOff + (bq + 16 * j) * 8);
        }
        __syncthreads();
    }

#pragma unroll
    for (int f = 0; f < 2; f++) {
#pragma unroll
        for (int g = 0; g < NF; g++) {
            int r0 = m0 + wm * 32 + f * 16 + (lane >> 2);
            int col = n0 + wn * WN + g * 8 + (lane & 3) * 2;
            float* p = Cout + (size_t)r0 * NG + col;
            *(float2*)p = make_float2(acc[f][g][0], acc[f][g][1]);
            *(float2*)(p + 8 * NG) = make_float2(acc[f][g][2], acc[f][g][3]);
        }
    }
}

// ---------------- elementwise h: writes fp16 ----------------
__global__ void h_kernel(const float* __restrict__ usp, const float* __restrict__ vsp) {
    const float SQRT_D = 22.62741699796952f;
    int i4 = blockIdx.x * blockDim.x + threadIdx.x;
    if (i4 >= Mm * Ff / 4) return;
    int m  = i4 >> 8;
    int f  = (i4 & 255) * 4;
    int l  = m & 127;

    float4 u  = *(const float4*)(g_U   + (size_t)m * Ff + f);
    float4 v  = *(const float4*)(g_V   + (size_t)m * Ff + f);
    float4 ig = *(const float4*)(g_ing + (size_t)l * Ff + f);
    float4 iu = *(const float4*)(g_inu + (size_t)l * Ff + f);
    float4 us = *(const float4*)(usp + f);
    float4 vs = *(const float4*)(vsp + f);

    float4 h;
    { float uu = u.x * ig.x, vv = v.x * iu.x; float zz = fabsf(vs.x) * SQRT_D * vv;
      h.x = (zz / (1.f + expf(-zz))) * (fabsf(us.x) * uu); }
    { float uu = u.y * ig.y, vv = v.y * iu.y; float zz = fabsf(vs.y) * SQRT_D * vv;
      h.y = (zz / (1.f + expf(-zz))) * (fabsf(us.y) * uu); }
    { float uu = u.z * ig.z, vv = v.z * iu.z; float zz = fabsf(vs.z) * SQRT_D * vv;
      h.z = (zz / (1.f + expf(-zz))) * (fabsf(us.z) * uu); }
    { float uu = u.w * ig.w, vv = v.w * iu.w; float zz = fabsf(vs.w) * SQRT_D * vv;
      h.w = (zz / (1.f + expf(-zz))) * (fabsf(us.w) * uu); }

    __half2 o0 = __float22half2_rn(make_float2(h.x, h.y));
    __half2 o1 = __float22half2_rn(make_float2(h.z, h.w));
    *(uint2*)(((__half*)g_H) + (size_t)m * Ff + f) =
        make_uint2(*(uint32_t*)&o0, *(uint32_t*)&o1);
}

// ---------------- final: sum 4 split-K partials, apply down-norm, row L2 normalize ----------------
__global__ void out_kernel(float* __restrict__ out) {
    int m = blockIdx.x;
    int t = threadIdx.x;
    int l = m & 127;

    size_t off = (size_t)m * Dd + t * 4;
    float4 p0 = *(const float4*)(g_O + off);
    float4 p1 = *(const float4*)(g_U + off);
    float4 p2 = *(const float4*)(g_U + (size_t)Mm * Dd + off);
    float4 p3 = *(const float4*)(g_V + off);
    float4 iv = *(const float4*)(g_ind + (size_t)l * Dd + t * 4);

    float4 o;
    o.x = ((p0.x + p1.x) + (p2.x + p3.x)) * iv.x;
    o.y = ((p0.y + p1.y) + (p2.y + p3.y)) * iv.y;
    o.z = ((p0.z + p1.z) + (p2.z + p3.z)) * iv.z;
    o.w = ((p0.w + p1.w) + (p2.w + p3.w)) * iv.w;

    float ss = o.x*o.x + o.y*o.y + o.z*o.z + o.w*o.w;
#pragma unroll
    for (int offm = 16; offm > 0; offm >>= 1)
        ss += __shfl_xor_sync(0xffffffffu, ss, offm);

    __shared__ float ws[4];
    if ((t & 31) == 0) ws[t >> 5] = ss;
    __syncthreads();
    float tot = ws[0] + ws[1] + ws[2] + ws[3];
    float sc = 1.f / fmaxf(sqrtf(tot), 1e-12f);

    o.x *= sc; o.y *= sc; o.z *= sc; o.w *= sc;
    *(float4*)(out + off) = o;
}

// ---------------- launch ----------------
extern "C" void kernel_launch(void* const* d_in, const int* in_sizes, int n_in,
                              void* d_out, int out_size) {
    const float* x   = (const float*)d_in[0];
    const float* Wg  = (const float*)d_in[1];
    const float* Wu  = (const float*)d_in[2];
    const float* Wd  = (const float*)d_in[3];
    const float* t1  = (const float*)d_in[4];
    const float* t2  = (const float*)d_in[5];
    const float* t3  = (const float*)d_in[6];
    const float* usp = (const float*)d_in[7];
    const float* vsp = (const float*)d_in[8];
    float* out = (float*)d_out;

    const int DSMEM_UV = 128 * 1040 + 2 * 32 * 528;   // 166912
    const int DSMEM_DN = 2 * (128 * 80 + 32 * 528);   // 54272
    cudaFuncSetAttribute(gemm13, cudaFuncAttributeMaxDynamicSharedMemorySize, DSMEM_UV);
    cudaFuncSetAttribute(gemm14, cudaFuncAttributeMaxDynamicSharedMemorySize, DSMEM_DN);

    softmax_kernel<<<3, 128>>>(t1, t2, t3);
    // gram: planes gate, up, down[0:512), down[512:1024) -> 128 equal blocks
    gram_kernel<<<dim3(32, 4), 256>>>(Wg, Wu, Wd);
    norm_kernel<<<dim3(8, 16, 3), 128>>>();

    // U and V fused (z=0 -> U, z=1 -> V): persistent-x, BN=256, 128 blocks
    gemm13<<<dim3(4, 16, 2), 512, DSMEM_UV>>>(x, Wg, Wu);
    // h = silu(vs*v) * (us*u), stored fp16
    h_kernel<<<2048, 256>>>(usp, vsp);
    // O partials: split-K=4 -> g_O, g_U, g_U+1M, g_V
    gemm14<<<dim3(2, 16, 4), 512, DSMEM_DN>>>(Wd);
    // final: sum 4 partials + normalize
    out_kernel<<<2048, 128>>>(out);
}